// round 1
// baseline (speedup 1.0000x reference)
#include <cuda_runtime.h>
#include <cuda_bf16.h>

// ---------------------------------------------------------------------------
// Decoder_65111704207909: B=8192, T=20, H=128, K=5 sequential MDN-LSTM decoder
// Strategy: persistent-per-CTA recurrence. 28 batch rows per CTA (293 CTAs).
// h/c live in shared memory (transposed [k][row] for broadcast LDS in GEMM).
// GEMM inner loop uses packed fma.rn.f32x2 (2 fp32 FMA / inst).
// enc_h @ W (constant across steps) precomputed once into __device__ scratch.
// ---------------------------------------------------------------------------

#define Bsz 8192
#define Tt 20
#define Hh 128
#define KcK 5
#define NG 512                         // 4*H
#define ROWS 28
#define NCTA ((Bsz + ROWS - 1) / ROWS) // 293
#define NTHREADS 256
#define PRE_BB 16

typedef unsigned long long u64;

// scratch: enc_h @ W[:H] + b  (bias folded in), per LSTM
__device__ float g_encW_my[(size_t)Bsz * NG];
__device__ float g_encW_ff[(size_t)Bsz * NG];

__device__ __forceinline__ u64 pack2f(float x, float y) {
    u64 r; asm("mov.b64 %0, {%1, %2};" : "=l"(r) : "f"(x), "f"(y)); return r;
}
__device__ __forceinline__ u64 dup2f(float x) {
    u64 r; asm("mov.b64 %0, {%1, %1};" : "=l"(r) : "f"(x)); return r;
}
__device__ __forceinline__ void fma2(u64& d, u64 a, u64 b) {
    asm("fma.rn.f32x2 %0, %1, %2, %0;" : "+l"(d) : "l"(a), "l"(b));
}
__device__ __forceinline__ void unpack2(u64 v, float& x, float& y) {
    asm("mov.b64 {%0, %1}, %2;" : "=f"(x), "=f"(y) : "l"(v));
}
__device__ __forceinline__ float sigf(float x) { return 1.0f / (1.0f + expf(-x)); }

// ---------------------------------------------------------------------------
// Precompute: g_encW = state_h @ W[:H, :] + b   (both LSTMs), once per replay.
// 16 batch rows per block; thread t owns column pair (2t, 2t+1) of both mats.
// ---------------------------------------------------------------------------
__global__ __launch_bounds__(256) void precompute_kernel(
    const float* __restrict__ state_h,
    const float* __restrict__ W_my, const float* __restrict__ b_my,
    const float* __restrict__ W_ff, const float* __restrict__ b_ff)
{
    __shared__ float hsh[Hh * PRE_BB];  // transposed [k][bb]
    const int t = threadIdx.x;
    const int b0 = blockIdx.x * PRE_BB;

    for (int idx = t; idx < Hh * PRE_BB; idx += 256) {
        int k = idx / PRE_BB, bb = idx % PRE_BB;
        hsh[idx] = state_h[(size_t)(b0 + bb) * Hh + k];
    }
    __syncthreads();

    const int c0 = 2 * t;
    u64 accm[PRE_BB], accf[PRE_BB];
    u64 bm = pack2f(b_my[c0], b_my[c0 + 1]);
    u64 bf = pack2f(b_ff[c0], b_ff[c0 + 1]);
#pragma unroll
    for (int bb = 0; bb < PRE_BB; bb++) { accm[bb] = bm; accf[bb] = bf; }

    for (int k = 0; k < Hh; k++) {
        u64 wm = *(const u64*)&W_my[(size_t)k * NG + c0];
        u64 wf = *(const u64*)&W_ff[(size_t)k * NG + c0];
#pragma unroll
        for (int bb = 0; bb < PRE_BB; bb++) {
            u64 hh = dup2f(hsh[k * PRE_BB + bb]);
            fma2(accm[bb], hh, wm);
            fma2(accf[bb], hh, wf);
        }
    }
#pragma unroll
    for (int bb = 0; bb < PRE_BB; bb++) {
        *(u64*)&g_encW_my[(size_t)(b0 + bb) * NG + c0] = accm[bb];
        *(u64*)&g_encW_ff[(size_t)(b0 + bb) * NG + c0] = accf[bb];
    }
}

// ---------------------------------------------------------------------------
// One LSTM update for 28 rows. Thread (j = tid&127, rh = tid>>7) computes the
// 4 gate columns {j, j+128, j+256, j+384} for 14 rows (rows rh*14..+13).
// sh_h layout: [k][row] (stride ROWS). sh_c layout: [j][row].
// Contains one __syncthreads() separating "everyone read old h" from h write.
// ---------------------------------------------------------------------------
template <int NQ>
__device__ __forceinline__ void lstm_phase(
    const float* __restrict__ encW, const float* __restrict__ U,
    const float* sh_wt, const float* sh_cond,
    float* sh_h, float* sh_c,
    int j, int rbl, const int* ebase)
{
    u64 acc[4][7];

    // accumulator init: encW (has bias folded) + cond-tail @ W[H:, :]
#pragma unroll
    for (int g = 0; g < 4; g++) {
        const int col = g * 128 + j;
        float wq[NQ];
#pragma unroll
        for (int q = 0; q < NQ; q++) wq[q] = sh_wt[q * NG + col];
#pragma unroll
        for (int p = 0; p < 7; p++) {
            float a0 = encW[ebase[2 * p] + col];
            float a1 = encW[ebase[2 * p + 1] + col];
#pragma unroll
            for (int q = 0; q < NQ; q++) {
                a0 += sh_cond[q * ROWS + rbl + 2 * p] * wq[q];
                a1 += sh_cond[q * ROWS + rbl + 2 * p + 1] * wq[q];
            }
            acc[g][p] = pack2f(a0, a1);
        }
    }

    // main GEMM: acc += h[k][rows] * U[k][col]
#pragma unroll 4
    for (int k = 0; k < Hh; k++) {
        const float* urow = U + (size_t)k * NG + j;
        u64 u0 = dup2f(urow[0]);
        u64 u1 = dup2f(urow[128]);
        u64 u2 = dup2f(urow[256]);
        u64 u3 = dup2f(urow[384]);
        const u64* hp = (const u64*)(sh_h + k * ROWS + rbl);
#pragma unroll
        for (int p = 0; p < 7; p++) {
            u64 h2 = hp[p];
            fma2(acc[0][p], h2, u0);
            fma2(acc[1][p], h2, u1);
            fma2(acc[2][p], h2, u2);
            fma2(acc[3][p], h2, u3);
        }
    }

    // gate nonlinearities; c is private to (j, rh) pair -> no sync needed
    float hn[14];
#pragma unroll
    for (int p = 0; p < 7; p++) {
        float zi0, zi1, zf0, zf1, zg0, zg1, zo0, zo1;
        unpack2(acc[0][p], zi0, zi1);
        unpack2(acc[1][p], zf0, zf1);
        unpack2(acc[2][p], zg0, zg1);
        unpack2(acc[3][p], zo0, zo1);
        const int r0 = rbl + 2 * p;
        float c0 = sh_c[j * ROWS + r0];
        float c1 = sh_c[j * ROWS + r0 + 1];
        float c20 = sigf(zf0) * c0 + sigf(zi0) * tanhf(zg0);
        float c21 = sigf(zf1) * c1 + sigf(zi1) * tanhf(zg1);
        sh_c[j * ROWS + r0] = c20;
        sh_c[j * ROWS + r0 + 1] = c21;
        hn[2 * p] = sigf(zo0) * tanhf(c20);
        hn[2 * p + 1] = sigf(zo1) * tanhf(c21);
    }

    __syncthreads();  // all threads done reading old sh_h
#pragma unroll
    for (int p = 0; p < 7; p++) {
        *(u64*)(sh_h + j * ROWS + rbl + 2 * p) = pack2f(hn[2 * p], hn[2 * p + 1]);
    }
}

// ---------------------------------------------------------------------------
// Main persistent kernel: whole T=20 recurrence per CTA.
// ---------------------------------------------------------------------------
__global__ __launch_bounds__(NTHREADS, 2) void decoder_kernel(
    const float* __restrict__ cond_m, const float* __restrict__ cond_y,
    const float* __restrict__ cond_f, const float* __restrict__ cond_fa,
    const float* __restrict__ state_h, const float* __restrict__ state_c,
    const float* __restrict__ W_my, const float* __restrict__ U_my,
    const float* __restrict__ W_ff, const float* __restrict__ U_ff,
    const float* __restrict__ Wh_my, const float* __restrict__ bh_my,
    const float* __restrict__ Wh_ff, const float* __restrict__ bh_ff,
    const float* __restrict__ gumbel, const float* __restrict__ znorm,
    float* __restrict__ out)
{
    extern __shared__ float smem[];
    float* sh_h_my  = smem;                      // Hh*ROWS, layout [k][row]
    float* sh_h_ff  = sh_h_my + Hh * ROWS;
    float* sh_c_my  = sh_h_ff + Hh * ROWS;       // layout [j][row]
    float* sh_c_ff  = sh_c_my + Hh * ROWS;
    float* sh_wt_my = sh_c_ff + Hh * ROWS;       // 5*NG (W_my rows 128..132)
    float* sh_wt_ff = sh_wt_my + 5 * NG;         // 2*NG
    float* sh_cond5 = sh_wt_ff + 2 * NG;         // [q][row], 5*ROWS
    float* sh_cond2 = sh_cond5 + 5 * ROWS;       // 2*ROWS
    float* sh_rmy   = sh_cond2 + 2 * ROWS;       // [row][45]
    float* sh_rff   = sh_rmy + ROWS * 45;        // [row][30]

    const int tid = threadIdx.x;
    const int rowbase = blockIdx.x * ROWS;

    // ---- init shared state ----
    for (int idx = tid; idx < Hh * ROWS; idx += NTHREADS) {
        int k = idx / ROWS, row = idx % ROWS;
        int b = min(rowbase + row, Bsz - 1);
        float hv = state_h[(size_t)b * Hh + k];
        float cv = state_c[(size_t)b * Hh + k];
        sh_h_my[idx] = hv; sh_h_ff[idx] = hv;
        sh_c_my[k * ROWS + row] = cv; sh_c_ff[k * ROWS + row] = cv;
    }
    for (int idx = tid; idx < 5 * NG; idx += NTHREADS)
        sh_wt_my[idx] = W_my[(size_t)Hh * NG + idx];
    for (int idx = tid; idx < 2 * NG; idx += NTHREADS)
        sh_wt_ff[idx] = W_ff[(size_t)Hh * NG + idx];
    if (tid < ROWS) {
        int row = tid;
        int b = min(rowbase + row, Bsz - 1);
        float m0 = cond_m[((size_t)b * Tt + 0) * 2 + 0];
        float m1 = cond_m[((size_t)b * Tt + 0) * 2 + 1];
        float y0 = cond_y[(size_t)b * Tt + 0];
        float f0 = cond_f[(size_t)b * Tt + 0];
        float a0 = cond_fa[(size_t)b * Tt + 0];
        sh_cond5[0 * ROWS + row] = m0;
        sh_cond5[1 * ROWS + row] = m1;
        sh_cond5[2 * ROWS + row] = y0;
        sh_cond5[3 * ROWS + row] = f0;
        sh_cond5[4 * ROWS + row] = a0;
        sh_cond2[0 * ROWS + row] = f0;
        sh_cond2[1 * ROWS + row] = a0;
    }
    __syncthreads();

    const int j = tid & 127;
    const int rh = tid >> 7;
    const int rbl = rh * 14;
    int ebase[14];
#pragma unroll
    for (int r = 0; r < 14; r++)
        ebase[r] = min(rowbase + rbl + r, Bsz - 1) * NG;

    float* out_gm  = out;
    float* out_gy  = out + (size_t)Bsz * Tt * 30;
    float* out_gf  = out + (size_t)Bsz * Tt * 45;
    float* out_gfa = out + (size_t)Bsz * Tt * 60;

    for (int t = 0; t < Tt; t++) {
        // ===== LSTM my then ff =====
        lstm_phase<5>(g_encW_my, U_my, sh_wt_my, sh_cond5, sh_h_my, sh_c_my, j, rbl, ebase);
        lstm_phase<2>(g_encW_ff, U_ff, sh_wt_ff, sh_cond2, sh_h_ff, sh_c_ff, j, rbl, ebase);
        __syncthreads();  // new h_my / h_ff visible to everyone

        // ===== heads: r_my = h_my @ Wh_my + bh_my ; r_ff similarly =====
        {
            const int warp = tid >> 5, lane = tid & 31;
#pragma unroll
            for (int i = 0; i < 4; i++) {
                int row = warp + 8 * i;
                if (row < ROWS) {
                    float a[3];
#pragma unroll
                    for (int cc = 0; cc < 3; cc++) {
                        int c = lane + 32 * cc;
                        a[cc] = (c < 45) ? bh_my[c] : ((c < 75) ? bh_ff[c - 45] : 0.0f);
                    }
                    for (int k = 0; k < Hh; k++) {
                        float hm = sh_h_my[k * ROWS + row];
                        float hf = sh_h_ff[k * ROWS + row];
#pragma unroll
                        for (int cc = 0; cc < 3; cc++) {
                            int c = lane + 32 * cc;
                            if (c < 45)      a[cc] += hm * Wh_my[k * 45 + c];
                            else if (c < 75) a[cc] += hf * Wh_ff[k * 30 + (c - 45)];
                        }
                    }
#pragma unroll
                    for (int cc = 0; cc < 3; cc++) {
                        int c = lane + 32 * cc;
                        if (c < 45)      sh_rmy[row * 45 + c] = a[cc];
                        else if (c < 75) sh_rff[row * 30 + (c - 45)] = a[cc];
                    }
                }
            }
        }
        __syncthreads();  // r buffers ready

        // ===== sampling / cond update / outputs =====
        if (tid < 4 * ROWS) {
            const int row = tid >> 2;
            const int d = tid & 3;
            const bool valid = (rowbase + row) < Bsz;
            const int b = min(rowbase + row, Bsz - 1);
            const int tn = min(t + 1, Tt - 1);
            const float* gum = gumbel + (((size_t)t * 4 + d) * Bsz + b) * KcK;
            const float* zn  = znorm + ((size_t)t * Bsz + b) * 5;

            if (d == 0) {
                float lg[5], mul[5], sl[5], mulat[5], slat[5], rho[5];
#pragma unroll
                for (int k = 0; k < 5; k++) {
                    lg[k]    = sh_rmy[row * 45 + k];
                    mul[k]   = sh_rmy[row * 45 + 5 + k];
                    sl[k]    = expf(sh_rmy[row * 45 + 10 + k]);
                    mulat[k] = sh_rmy[row * 45 + 15 + k];
                    slat[k]  = expf(sh_rmy[row * 45 + 20 + k]);
                    rho[k]   = tanhf(sh_rmy[row * 45 + 25 + k]);
                }
                // softmax
                float mx = lg[0];
#pragma unroll
                for (int k = 1; k < 5; k++) mx = fmaxf(mx, lg[k]);
                float am[5], ssum = 0.0f;
#pragma unroll
                for (int k = 0; k < 5; k++) { am[k] = expf(lg[k] - mx); ssum += am[k]; }
                float inv = 1.0f / ssum;
#pragma unroll
                for (int k = 0; k < 5; k++) am[k] *= inv;
                // argmax(log a + g) == argmax(logits + g)
                int im = 0; float best = lg[0] + gum[0];
#pragma unroll
                for (int k = 1; k < 5; k++) {
                    float v = lg[k] + gum[k];
                    if (v > best) { best = v; im = k; }
                }
                float z1 = zn[0], z2 = zn[1];
                float rr = rho[im];
                float s_long = mul[im] + sl[im] * z1;
                float s_lt = mulat[im] + slat[im] * (rr * z1 + sqrtf(fmaxf(1.0f - rr * rr, 0.0f)) * z2);
                float nm0 = cond_m[((size_t)b * Tt + tn) * 2 + 0];
                float nm1 = cond_m[((size_t)b * Tt + tn) * 2 + 1];
                float cm0 = (fabsf(s_long - nm0) < 0.3f) ? s_long : nm0;
                float cm1 = (fabsf(s_lt  - nm1) < 0.1f) ? s_lt  : nm1;
                sh_cond5[0 * ROWS + row] = cm0;
                sh_cond5[1 * ROWS + row] = cm1;
                if (valid) {
                    float* o = out_gm + ((size_t)b * Tt + t) * 30;
#pragma unroll
                    for (int k = 0; k < 5; k++) {
                        o[k] = am[k]; o[5 + k] = mul[k]; o[10 + k] = sl[k];
                        o[15 + k] = mulat[k]; o[20 + k] = slat[k]; o[25 + k] = rho[k];
                    }
                }
            } else {
                const float* rbase;
                float zv, nv;
                float* osec;
                if (d == 1) {
                    rbase = sh_rmy + row * 45 + 30; zv = zn[2];
                    nv = cond_y[(size_t)b * Tt + tn]; osec = out_gy;
                } else if (d == 2) {
                    rbase = sh_rff + row * 30; zv = zn[3];
                    nv = cond_f[(size_t)b * Tt + tn]; osec = out_gf;
                } else {
                    rbase = sh_rff + row * 30 + 15; zv = zn[4];
                    nv = cond_fa[(size_t)b * Tt + tn]; osec = out_gfa;
                }
                float lg[5], mu[5], s[5];
#pragma unroll
                for (int k = 0; k < 5; k++) {
                    lg[k] = rbase[k]; mu[k] = rbase[5 + k]; s[k] = expf(rbase[10 + k]);
                }
                float mx = lg[0];
#pragma unroll
                for (int k = 1; k < 5; k++) mx = fmaxf(mx, lg[k]);
                float am[5], ssum = 0.0f;
#pragma unroll
                for (int k = 0; k < 5; k++) { am[k] = expf(lg[k] - mx); ssum += am[k]; }
                float inv = 1.0f / ssum;
#pragma unroll
                for (int k = 0; k < 5; k++) am[k] *= inv;
                int im = 0; float best = lg[0] + gum[0];
#pragma unroll
                for (int k = 1; k < 5; k++) {
                    float v = lg[k] + gum[k];
                    if (v > best) { best = v; im = k; }
                }
                float samp = mu[im] + s[im] * zv;
                float cn = (fabsf(samp - nv) < 0.3f) ? samp : nv;
                if (d == 1) {
                    sh_cond5[2 * ROWS + row] = cn;
                } else if (d == 2) {
                    sh_cond5[3 * ROWS + row] = cn;
                    sh_cond2[0 * ROWS + row] = cn;
                } else {
                    sh_cond5[4 * ROWS + row] = cn;
                    sh_cond2[1 * ROWS + row] = cn;
                }
                if (valid) {
                    float* o = osec + ((size_t)b * Tt + t) * 15;
#pragma unroll
                    for (int k = 0; k < 5; k++) {
                        o[k] = am[k]; o[5 + k] = mu[k]; o[10 + k] = s[k];
                    }
                }
            }
        }
        __syncthreads();  // cond5/cond2 updated for next step
    }
}

// ---------------------------------------------------------------------------
extern "C" void kernel_launch(void* const* d_in, const int* in_sizes, int n_in,
                              void* d_out, int out_size)
{
    (void)in_sizes; (void)n_in; (void)out_size;
    const float* cond_m  = (const float*)d_in[0];
    const float* cond_y  = (const float*)d_in[1];
    const float* cond_f  = (const float*)d_in[2];
    const float* cond_fa = (const float*)d_in[3];
    const float* state_h = (const float*)d_in[4];
    const float* state_c = (const float*)d_in[5];
    const float* W_my    = (const float*)d_in[6];
    const float* U_my    = (const float*)d_in[7];
    const float* b_my    = (const float*)d_in[8];
    const float* W_ff    = (const float*)d_in[9];
    const float* U_ff    = (const float*)d_in[10];
    const float* b_ff    = (const float*)d_in[11];
    const float* Wh_my   = (const float*)d_in[12];
    const float* bh_my   = (const float*)d_in[13];
    const float* Wh_ff   = (const float*)d_in[14];
    const float* bh_ff   = (const float*)d_in[15];
    const float* gumbel  = (const float*)d_in[16];
    const float* znorm   = (const float*)d_in[17];
    float* out = (float*)d_out;

    const int smem_bytes =
        (4 * Hh * ROWS + 5 * NG + 2 * NG + 5 * ROWS + 2 * ROWS + ROWS * 45 + ROWS * 30)
        * (int)sizeof(float);  // 80864 B

    cudaFuncSetAttribute(decoder_kernel,
                         cudaFuncAttributeMaxDynamicSharedMemorySize, smem_bytes);

    precompute_kernel<<<Bsz / PRE_BB, 256>>>(state_h, W_my, b_my, W_ff, b_ff);
    decoder_kernel<<<NCTA, NTHREADS, smem_bytes>>>(
        cond_m, cond_y, cond_f, cond_fa, state_h, state_c,
        W_my, U_my, W_ff, U_ff, Wh_my, bh_my, Wh_ff, bh_ff,
        gumbel, znorm, out);
}

// round 2
// speedup vs baseline: 1.6431x; 1.6431x over previous
#include <cuda_runtime.h>
#include <cuda_bf16.h>

// ---------------------------------------------------------------------------
// Decoder_65111704207909  (B=8192, T=20, H=128, K=5)
// Round 2: persistent CTA (56 rows), 512 thr, 1 CTA/SM, grid=147 (1 even wave).
//  - U staged via cp.async double-buffer (kills lockstep L2 stalls)
//  - c state in registers; Wh heads cached in SMEM; packed f32x2 everywhere
//  - fast ex2/rcp-based sigmoid/tanh/exp
// ---------------------------------------------------------------------------

#define Bsz 8192
#define Tt 20
#define Hh 128
#define KcK 5
#define NG 512                  // 4*H
#define ROWS 56
#define NCTA 147                // ceil(8192/56)
#define NTHREADS 512
#define HSTR 58                 // padded row stride for [k][row] arrays
#define KCH 16                  // k-rows per staged chunk
#define NCHUNK (Hh / KCH)       // 8
#define PRE_BB 16

typedef unsigned long long u64;

// enc_h @ W[:H] + b (bias folded), per LSTM — constant across steps
__device__ float g_encW_my[(size_t)Bsz * NG];
__device__ float g_encW_ff[(size_t)Bsz * NG];

__device__ __forceinline__ u64 pack2f(float x, float y) {
    u64 r; asm("mov.b64 %0, {%1, %2};" : "=l"(r) : "f"(x), "f"(y)); return r;
}
__device__ __forceinline__ u64 dup2f(float x) {
    u64 r; asm("mov.b64 %0, {%1, %1};" : "=l"(r) : "f"(x)); return r;
}
__device__ __forceinline__ void fma2(u64& d, u64 a, u64 b) {
    asm("fma.rn.f32x2 %0, %1, %2, %0;" : "+l"(d) : "l"(a), "l"(b));
}
__device__ __forceinline__ void unpack2(u64 v, float& x, float& y) {
    asm("mov.b64 {%0, %1}, %2;" : "=f"(x), "=f"(y) : "l"(v));
}

// ---- fast transcendentals (ex2/rcp approx: rel err ~1e-6, margin is 50x) ----
__device__ __forceinline__ float ex2f(float x) {
    float y; asm("ex2.approx.f32 %0, %1;" : "=f"(y) : "f"(x)); return y;
}
__device__ __forceinline__ float rcpf(float x) {
    float y; asm("rcp.approx.f32 %0, %1;" : "=f"(y) : "f"(x)); return y;
}
#define LOG2E 1.4426950408889634f
__device__ __forceinline__ float sigf(float x) {
    return rcpf(1.0f + ex2f(-LOG2E * x));
}
__device__ __forceinline__ float tanhf_fast(float x) {
    // 1 - 2/(1+e^{2x}) ; saturates correctly at +-inf
    return fmaf(-2.0f, rcpf(1.0f + ex2f((2.0f * LOG2E) * x)), 1.0f);
}
__device__ __forceinline__ float expf_fast(float x) { return ex2f(LOG2E * x); }

// ---- cp.async helpers ----
__device__ __forceinline__ void stage_chunk(float* dst, const float* __restrict__ src, int tid) {
    unsigned smp = (unsigned)__cvta_generic_to_shared(dst);
#pragma unroll
    for (int i = 0; i < 4; i++) {
        asm volatile("cp.async.cg.shared.global [%0], [%1], 16;"
                     :: "r"(smp + (unsigned)((tid + i * NTHREADS) * 16)),
                        "l"(src + (size_t)(tid + i * NTHREADS) * 4)
                     : "memory");
    }
    asm volatile("cp.async.commit_group;" ::: "memory");
}
template <int N>
__device__ __forceinline__ void cp_wait() {
    asm volatile("cp.async.wait_group %0;" :: "n"(N) : "memory");
}

// ---------------------------------------------------------------------------
// Precompute: g_encW = state_h @ W[:H, :] + b (both LSTMs)
// ---------------------------------------------------------------------------
__global__ __launch_bounds__(256) void precompute_kernel(
    const float* __restrict__ state_h,
    const float* __restrict__ W_my, const float* __restrict__ b_my,
    const float* __restrict__ W_ff, const float* __restrict__ b_ff)
{
    __shared__ float hsh[Hh * PRE_BB];  // [k][bb]
    const int t = threadIdx.x;
    const int b0 = blockIdx.x * PRE_BB;

    for (int idx = t; idx < Hh * PRE_BB; idx += 256) {
        int k = idx / PRE_BB, bb = idx % PRE_BB;
        hsh[idx] = state_h[(size_t)(b0 + bb) * Hh + k];
    }
    __syncthreads();

    const int c0 = 2 * t;
    u64 accm[PRE_BB], accf[PRE_BB];
    u64 bm = pack2f(b_my[c0], b_my[c0 + 1]);
    u64 bf = pack2f(b_ff[c0], b_ff[c0 + 1]);
#pragma unroll
    for (int bb = 0; bb < PRE_BB; bb++) { accm[bb] = bm; accf[bb] = bf; }

    for (int k = 0; k < Hh; k++) {
        u64 wm = *(const u64*)&W_my[(size_t)k * NG + c0];
        u64 wf = *(const u64*)&W_ff[(size_t)k * NG + c0];
#pragma unroll
        for (int bb = 0; bb < PRE_BB; bb++) {
            u64 hh = dup2f(hsh[k * PRE_BB + bb]);
            fma2(accm[bb], hh, wm);
            fma2(accf[bb], hh, wf);
        }
    }
#pragma unroll
    for (int bb = 0; bb < PRE_BB; bb++) {
        *(u64*)&g_encW_my[(size_t)(b0 + bb) * NG + c0] = accm[bb];
        *(u64*)&g_encW_ff[(size_t)(b0 + bb) * NG + c0] = accf[bb];
    }
}

// ---------------------------------------------------------------------------
// One LSTM update. Thread (j = tid&127, g = tid>>7) computes gate columns
// {j, j+128, j+256, j+384} for rows g*14..g*14+13 (7 row-pairs, packed f32x2).
// U streamed global->smem via cp.async double-buffer. c kept in registers.
// ---------------------------------------------------------------------------
template <int NQ>
__device__ __forceinline__ void lstm_phase(
    const float* __restrict__ encW, const float* __restrict__ Ug,
    const float* sh_wt, const float* sh_cond, float* sh_h, float* sh_U,
    float (&c)[14], int j, int rbl, const int* ebase, int tid)
{
    stage_chunk(sh_U, Ug, tid);  // chunk 0 -> buffer 0

    // ---- accumulator init: encW (bias folded) + cond-tail @ W[H:, :] ----
    u64 acc[4][7];
#pragma unroll
    for (int g4 = 0; g4 < 4; g4++) {
        const int col = g4 * 128 + j;
#pragma unroll
        for (int p = 0; p < 7; p++)
            acc[g4][p] = pack2f(encW[ebase[2 * p] + col], encW[ebase[2 * p + 1] + col]);
    }
#pragma unroll
    for (int q = 0; q < NQ; q++) {
        u64 cpp[7];
#pragma unroll
        for (int p = 0; p < 7; p++)
            cpp[p] = *(const u64*)(sh_cond + q * HSTR + rbl + 2 * p);
#pragma unroll
        for (int g4 = 0; g4 < 4; g4++) {
            u64 wd = dup2f(sh_wt[q * NG + g4 * 128 + j]);
#pragma unroll
            for (int p = 0; p < 7; p++) fma2(acc[g4][p], cpp[p], wd);
        }
    }

    // ---- main GEMM over staged chunks ----
    for (int ch = 0; ch < NCHUNK; ch++) {
        if (ch + 1 < NCHUNK) {
            stage_chunk(sh_U + ((ch + 1) & 1) * KCH * NG, Ug + (size_t)(ch + 1) * KCH * NG, tid);
            cp_wait<1>();
        } else {
            cp_wait<0>();
        }
        __syncthreads();
        const float* ub = sh_U + (ch & 1) * KCH * NG;
        const float* hb = sh_h + (ch * KCH) * HSTR + rbl;
#pragma unroll 4
        for (int kk = 0; kk < KCH; kk++) {
            const float* ur = ub + kk * NG + j;
            u64 u0 = dup2f(ur[0]);
            u64 u1 = dup2f(ur[128]);
            u64 u2 = dup2f(ur[256]);
            u64 u3 = dup2f(ur[384]);
            const u64* hp = (const u64*)(hb + kk * HSTR);
#pragma unroll
            for (int p = 0; p < 7; p++) {
                u64 h2 = hp[p];
                fma2(acc[0][p], h2, u0);
                fma2(acc[1][p], h2, u1);
                fma2(acc[2][p], h2, u2);
                fma2(acc[3][p], h2, u3);
            }
        }
        __syncthreads();  // everyone done with this buffer (and, last iter, with old h)
    }

    // ---- gate nonlinearities; c is register-private ----
    float hn[14];
#pragma unroll
    for (int p = 0; p < 7; p++) {
        float zi0, zi1, zf0, zf1, zg0, zg1, zo0, zo1;
        unpack2(acc[0][p], zi0, zi1);
        unpack2(acc[1][p], zf0, zf1);
        unpack2(acc[2][p], zg0, zg1);
        unpack2(acc[3][p], zo0, zo1);
        float c20 = sigf(zf0) * c[2 * p]     + sigf(zi0) * tanhf_fast(zg0);
        float c21 = sigf(zf1) * c[2 * p + 1] + sigf(zi1) * tanhf_fast(zg1);
        c[2 * p] = c20; c[2 * p + 1] = c21;
        hn[2 * p]     = sigf(zo0) * tanhf_fast(c20);
        hn[2 * p + 1] = sigf(zo1) * tanhf_fast(c21);
    }
#pragma unroll
    for (int p = 0; p < 7; p++)
        *(u64*)(sh_h + j * HSTR + rbl + 2 * p) = pack2f(hn[2 * p], hn[2 * p + 1]);
}

// ---------------------------------------------------------------------------
__global__ __launch_bounds__(NTHREADS, 1) void decoder_kernel(
    const float* __restrict__ cond_m, const float* __restrict__ cond_y,
    const float* __restrict__ cond_f, const float* __restrict__ cond_fa,
    const float* __restrict__ state_h, const float* __restrict__ state_c,
    const float* __restrict__ U_my, const float* __restrict__ U_ff,
    const float* __restrict__ W_my, const float* __restrict__ W_ff,
    const float* __restrict__ Wh_my, const float* __restrict__ bh_my,
    const float* __restrict__ Wh_ff, const float* __restrict__ bh_ff,
    const float* __restrict__ gumbel, const float* __restrict__ znorm,
    float* __restrict__ out)
{
    extern __shared__ float smem[];
    float* sh_U     = smem;                        // 2*KCH*NG = 16384 (16B aligned)
    float* sh_h_my  = sh_U + 2 * KCH * NG;         // Hh*HSTR, [k][row]
    float* sh_h_ff  = sh_h_my + Hh * HSTR;
    float* sh_wt_my = sh_h_ff + Hh * HSTR;         // 5*NG
    float* sh_wt_ff = sh_wt_my + 5 * NG;           // 2*NG
    float* sh_wh    = sh_wt_ff + 2 * NG;           // Hh*76 combined heads
    float* sh_cond5 = sh_wh + Hh * 76;             // [q][HSTR]
    float* sh_cond2 = sh_cond5 + 5 * HSTR;
    float* sh_r     = sh_cond2 + 2 * HSTR;         // [row][76]: 0-44 rmy, 45-74 rff

    const int tid = threadIdx.x;
    const int rowbase = blockIdx.x * ROWS;
    const int j = tid & 127;
    const int g = tid >> 7;     // 0..3
    const int rbl = g * 14;

    // ---- init shared: h, head weights, W-tail, cond ----
    for (int idx = tid; idx < Hh * ROWS; idx += NTHREADS) {
        int k = idx / ROWS, row = idx % ROWS;
        int b = min(rowbase + row, Bsz - 1);
        float hv = state_h[(size_t)b * Hh + k];
        sh_h_my[k * HSTR + row] = hv;
        sh_h_ff[k * HSTR + row] = hv;
    }
    for (int idx = tid; idx < 5 * NG; idx += NTHREADS)
        sh_wt_my[idx] = W_my[(size_t)Hh * NG + idx];
    for (int idx = tid; idx < 2 * NG; idx += NTHREADS)
        sh_wt_ff[idx] = W_ff[(size_t)Hh * NG + idx];
    for (int idx = tid; idx < Hh * 76; idx += NTHREADS) {
        int k = idx / 76, cc = idx % 76;
        float v = 0.0f;
        if (cc < 45)      v = Wh_my[k * 45 + cc];
        else if (cc < 75) v = Wh_ff[k * 30 + (cc - 45)];
        sh_wh[idx] = v;
    }
    if (tid < ROWS) {
        int row = tid;
        int b = min(rowbase + row, Bsz - 1);
        float m0 = cond_m[((size_t)b * Tt) * 2 + 0];
        float m1 = cond_m[((size_t)b * Tt) * 2 + 1];
        float y0 = cond_y[(size_t)b * Tt];
        float f0 = cond_f[(size_t)b * Tt];
        float a0 = cond_fa[(size_t)b * Tt];
        sh_cond5[0 * HSTR + row] = m0;
        sh_cond5[1 * HSTR + row] = m1;
        sh_cond5[2 * HSTR + row] = y0;
        sh_cond5[3 * HSTR + row] = f0;
        sh_cond5[4 * HSTR + row] = a0;
        sh_cond2[0 * HSTR + row] = f0;
        sh_cond2[1 * HSTR + row] = a0;
    }

    // ---- c state in registers (thread owns col j of rows rbl..rbl+13) ----
    float cmy[14], cff[14];
    int ebase[14];
#pragma unroll
    for (int r = 0; r < 14; r++) {
        int b = min(rowbase + rbl + r, Bsz - 1);
        ebase[r] = b * NG;
        float cv = state_c[(size_t)b * Hh + j];
        cmy[r] = cv; cff[r] = cv;
    }

    // head-phase constants
    const int hcc = tid >> 2;        // 0..127 (active < 75)
    const int hq = tid & 3;          // row group 0..3
    float bh = 0.0f;
    if (hcc < 45) bh = bh_my[hcc];
    else if (hcc < 75) bh = bh_ff[hcc - 45];

    float* out_gm  = out;
    float* out_gy  = out + (size_t)Bsz * Tt * 30;
    float* out_gf  = out + (size_t)Bsz * Tt * 45;
    float* out_gfa = out + (size_t)Bsz * Tt * 60;

    __syncthreads();

    for (int t = 0; t < Tt; t++) {
        lstm_phase<5>(g_encW_my, U_my, sh_wt_my, sh_cond5, sh_h_my, sh_U, cmy, j, rbl, ebase, tid);
        lstm_phase<2>(g_encW_ff, U_ff, sh_wt_ff, sh_cond2, sh_h_ff, sh_U, cff, j, rbl, ebase, tid);
        __syncthreads();  // h_my / h_ff visible

        // ===== heads: packed f32x2 over row pairs, weights from SMEM =====
        if (hcc < 75) {
            const float* hsrc = (hcc < 45) ? sh_h_my : sh_h_ff;
            const float* hb = hsrc + hq * 14;
            u64 a[7];
            u64 binit = dup2f(bh);
#pragma unroll
            for (int p = 0; p < 7; p++) a[p] = binit;
#pragma unroll 4
            for (int k = 0; k < Hh; k++) {
                u64 wd = dup2f(sh_wh[k * 76 + hcc]);
                const u64* hp = (const u64*)(hb + k * HSTR);
#pragma unroll
                for (int p = 0; p < 7; p++) fma2(a[p], hp[p], wd);
            }
#pragma unroll
            for (int p = 0; p < 7; p++) {
                float v0, v1;
                unpack2(a[p], v0, v1);
                int row = hq * 14 + 2 * p;
                sh_r[row * 76 + hcc] = v0;
                sh_r[(row + 1) * 76 + hcc] = v1;
            }
        }
        __syncthreads();

        // ===== sampling / cond update / outputs =====
        if (tid < 4 * ROWS) {
            const int row = tid >> 2;
            const int d = tid & 3;
            const bool valid = (rowbase + row) < Bsz;
            const int b = min(rowbase + row, Bsz - 1);
            const int tn = min(t + 1, Tt - 1);
            const float* gum = gumbel + (((size_t)t * 4 + d) * Bsz + b) * KcK;
            const float* zn = znorm + ((size_t)t * Bsz + b) * 5;

            if (d == 0) {
                const float* rb = sh_r + row * 76;
                float lg[5], mul[5], sl[5], mulat[5], slat[5], rho[5];
#pragma unroll
                for (int k = 0; k < 5; k++) {
                    lg[k]    = rb[k];
                    mul[k]   = rb[5 + k];
                    sl[k]    = expf_fast(rb[10 + k]);
                    mulat[k] = rb[15 + k];
                    slat[k]  = expf_fast(rb[20 + k]);
                    rho[k]   = tanhf_fast(rb[25 + k]);
                }
                float mx = lg[0];
#pragma unroll
                for (int k = 1; k < 5; k++) mx = fmaxf(mx, lg[k]);
                float am[5], ssum = 0.0f;
#pragma unroll
                for (int k = 0; k < 5; k++) { am[k] = expf_fast(lg[k] - mx); ssum += am[k]; }
                float inv = 1.0f / ssum;
#pragma unroll
                for (int k = 0; k < 5; k++) am[k] *= inv;
                int im = 0; float best = lg[0] + gum[0];
#pragma unroll
                for (int k = 1; k < 5; k++) {
                    float v = lg[k] + gum[k];
                    if (v > best) { best = v; im = k; }
                }
                float z1 = zn[0], z2 = zn[1];
                float rr = rho[im];
                float s_long = mul[im] + sl[im] * z1;
                float s_lt = mulat[im] + slat[im] * (rr * z1 + sqrtf(fmaxf(1.0f - rr * rr, 0.0f)) * z2);
                float nm0 = cond_m[((size_t)b * Tt + tn) * 2 + 0];
                float nm1 = cond_m[((size_t)b * Tt + tn) * 2 + 1];
                sh_cond5[0 * HSTR + row] = (fabsf(s_long - nm0) < 0.3f) ? s_long : nm0;
                sh_cond5[1 * HSTR + row] = (fabsf(s_lt  - nm1) < 0.1f) ? s_lt  : nm1;
                if (valid) {
                    float* o = out_gm + ((size_t)b * Tt + t) * 30;
#pragma unroll
                    for (int k = 0; k < 5; k++) {
                        o[k] = am[k]; o[5 + k] = mul[k]; o[10 + k] = sl[k];
                        o[15 + k] = mulat[k]; o[20 + k] = slat[k]; o[25 + k] = rho[k];
                    }
                }
            } else {
                const float* rb;
                float zv, nv;
                float* osec;
                if (d == 1) {
                    rb = sh_r + row * 76 + 30; zv = zn[2];
                    nv = cond_y[(size_t)b * Tt + tn]; osec = out_gy;
                } else if (d == 2) {
                    rb = sh_r + row * 76 + 45; zv = zn[3];
                    nv = cond_f[(size_t)b * Tt + tn]; osec = out_gf;
                } else {
                    rb = sh_r + row * 76 + 60; zv = zn[4];
                    nv = cond_fa[(size_t)b * Tt + tn]; osec = out_gfa;
                }
                float lg[5], mu[5], s[5];
#pragma unroll
                for (int k = 0; k < 5; k++) {
                    lg[k] = rb[k]; mu[k] = rb[5 + k]; s[k] = expf_fast(rb[10 + k]);
                }
                float mx = lg[0];
#pragma unroll
                for (int k = 1; k < 5; k++) mx = fmaxf(mx, lg[k]);
                float am[5], ssum = 0.0f;
#pragma unroll
                for (int k = 0; k < 5; k++) { am[k] = expf_fast(lg[k] - mx); ssum += am[k]; }
                float inv = 1.0f / ssum;
#pragma unroll
                for (int k = 0; k < 5; k++) am[k] *= inv;
                int im = 0; float best = lg[0] + gum[0];
#pragma unroll
                for (int k = 1; k < 5; k++) {
                    float v = lg[k] + gum[k];
                    if (v > best) { best = v; im = k; }
                }
                float samp = mu[im] + s[im] * zv;
                float cn = (fabsf(samp - nv) < 0.3f) ? samp : nv;
                if (d == 1) {
                    sh_cond5[2 * HSTR + row] = cn;
                } else if (d == 2) {
                    sh_cond5[3 * HSTR + row] = cn;
                    sh_cond2[0 * HSTR + row] = cn;
                } else {
                    sh_cond5[4 * HSTR + row] = cn;
                    sh_cond2[1 * HSTR + row] = cn;
                }
                if (valid) {
                    float* o = osec + ((size_t)b * Tt + t) * 15;
#pragma unroll
                    for (int k = 0; k < 5; k++) {
                        o[k] = am[k]; o[5 + k] = mu[k]; o[10 + k] = s[k];
                    }
                }
            }
        }
        __syncthreads();  // cond updated for next step
    }
}

// ---------------------------------------------------------------------------
extern "C" void kernel_launch(void* const* d_in, const int* in_sizes, int n_in,
                              void* d_out, int out_size)
{
    (void)in_sizes; (void)n_in; (void)out_size;
    const float* cond_m  = (const float*)d_in[0];
    const float* cond_y  = (const float*)d_in[1];
    const float* cond_f  = (const float*)d_in[2];
    const float* cond_fa = (const float*)d_in[3];
    const float* state_h = (const float*)d_in[4];
    const float* state_c = (const float*)d_in[5];
    const float* W_my    = (const float*)d_in[6];
    const float* U_my    = (const float*)d_in[7];
    const float* b_my    = (const float*)d_in[8];
    const float* W_ff    = (const float*)d_in[9];
    const float* U_ff    = (const float*)d_in[10];
    const float* b_ff    = (const float*)d_in[11];
    const float* Wh_my   = (const float*)d_in[12];
    const float* bh_my   = (const float*)d_in[13];
    const float* Wh_ff   = (const float*)d_in[14];
    const float* bh_ff   = (const float*)d_in[15];
    const float* gumbel  = (const float*)d_in[16];
    const float* znorm   = (const float*)d_in[17];
    float* out = (float*)d_out;

    const int smem_floats = 2 * KCH * NG + 2 * Hh * HSTR + 5 * NG + 2 * NG +
                            Hh * 76 + 7 * HSTR + ROWS * 76;
    const int smem_bytes = smem_floats * (int)sizeof(float);  // ~196.8 KB

    cudaFuncSetAttribute(decoder_kernel,
                         cudaFuncAttributeMaxDynamicSharedMemorySize, smem_bytes);

    precompute_kernel<<<Bsz / PRE_BB, 256>>>(state_h, W_my, b_my, W_ff, b_ff);
    decoder_kernel<<<NCTA, NTHREADS, smem_bytes>>>(
        cond_m, cond_y, cond_f, cond_fa, state_h, state_c,
        U_my, U_ff, W_my, W_ff, Wh_my, bh_my, Wh_ff, bh_ff,
        gumbel, znorm, out);
}